// round 3
// baseline (speedup 1.0000x reference)
#include <cuda_runtime.h>
#include <cuda_bf16.h>

#define DEV __device__ __forceinline__

// ---------------- scratch (no allocations allowed) ----------------
__device__ float g_s1l[32 * 256 * 16];   // stage1 LoTe out  [b,256,16]
__device__ float g_s1c[32 * 1024 * 16];  // stage1 Conv out  [b,1024,16]
__device__ float g_s2[32 * 64 * 32];     // stage2 out       [b,64,32] (lo2|co2)
__device__ float g_s3[32 * 16 * 32];     // stage3 out       [b,16,32] (lo3|co3)

// ---------------- gathers (exact unfold/reshape index math) ----------------
struct GLote1 {  // lx[b,a,p,l], a<48,p<256,l<4 from x[b,3,128,128], window 16
    const float* x;
    DEV float operator()(int b, int a, int p, int l) const {
        int flat = a * 1024 + p * 4 + l;
        int c = flat >> 14; int r = flat & 16383;
        int hb = r >> 11; r &= 2047;
        int wb = r >> 8;  r &= 255;
        int h = (hb << 4) + (r >> 4);
        int w = (wb << 4) + (r & 15);
        return x[((b * 3 + c) << 14) + (h << 7) + w];
    }
};
struct GConv1 {  // cx[b,a,p,l], a<16,p<1024,l<3, window 4
    const float* x;
    DEV float operator()(int b, int a, int p, int l) const {
        int flat = a * 3072 + p * 3 + l;
        int c = flat >> 14; int r = flat & 16383;
        int hb = r >> 9; r &= 511;
        int wb = r >> 4; r &= 15;
        int h = (hb << 2) + (r >> 2);
        int w = (wb << 2) + (r & 3);
        return x[((b * 3 + c) << 14) + (h << 7) + w];
    }
};
struct GComb {   // comb[b,a,p,l]: a<16,p<64,l<20; l<4 -> ly2, else cy2^T
    const float* ly;
    const float* cy;
    DEV float operator()(int b, int a, int p, int l) const {
        if (l < 4) {
            int r = (p << 2) + l;
            int hb = r >> 7; r &= 127;
            int wb = r >> 6; r &= 63;
            int h = (hb << 3) + (r >> 3);
            int w = (wb << 3) + (r & 7);
            return ly[(b * 256 + (a << 4) + h) * 16 + w];
        } else {
            int a2 = l - 4, l2 = a;
            int r = (p << 4) + l2;
            int hb = r >> 7; r &= 127;
            int wb = r >> 4; r &= 15;
            int h = (hb << 2) + (r >> 2);
            int w = (wb << 2) + (r & 3);
            int f3 = (a2 << 10) + (h << 5) + w;
            return cy[(b * 1024 + (f3 >> 4)) * 16 + (f3 & 15)];
        }
    }
};
struct GConv2 {
    GComb inner;
    DEV float operator()(int b, int a, int p, int l) const { return inner(b, l, p, a); }
};
struct GL3 {     // lx3[b,a,p,l], a<32,p<16,l<4 from grid[b,32,8,8]
    const float* s2;
    DEV float operator()(int b, int a, int p, int l) const {
        int r = (p << 2) + l;
        int hb = r >> 5; r &= 31;
        int wb = r >> 4; r &= 15;
        int h = (hb << 2) + (r >> 2);
        int w = (wb << 2) + (r & 3);
        int f3 = (a << 6) + (h << 3) + w;
        return s2[((b << 6) + (f3 >> 5)) * 32 + (f3 & 31)];
    }
};
struct GC3 {     // cx3[b,a,p,l], a<4,p<16,l<32, window 2
    const float* s2;
    DEV float operator()(int b, int a, int p, int l) const {
        int flat = (a << 9) + (p << 5) + l;
        int c = flat >> 6; int r = flat & 63;
        int hb = r >> 4; r &= 15;
        int wb = r >> 2; r &= 3;
        int h = (hb << 1) + (r >> 1);
        int w = (wb << 1) + (r & 1);
        int f3 = (c << 6) + (h << 3) + w;
        return s2[((b << 6) + (f3 >> 5)) * 32 + (f3 & 31)];
    }
};
struct GFin {    // xf[b,c,0,l] = y3bn[b,l,c]
    const float* s3;
    DEV float operator()(int b, int a, int /*p*/, int l) const {
        return s3[(((b << 4) + l) << 5) + a];
    }
};

// ---------------- generic per-patch MPS ----------------
// phi-fold: mats = sum_f x_f*(W_f - W_{f+Cn}) + sum_f W_{f+Cn}   (halves FMAs)
// W streamed with a 3-deep register prefetch ring; phi precomputed once for
// all l; 2 barriers per l (M publish, vS publish).
template <int Ln, int Fn, int NB, int On, typename G>
DEV void mps_patch(int p, int b0, const G& gth,
                   const float* __restrict__ cores,
                   const float* __restrict__ label,
                   float* __restrict__ out, int osb, int osp, int ooff)
{
    constexpr int Cn = Fn / 2;
    constexpr int Gn = Cn / 4;
    constexpr int PF = (Gn < 3) ? Gn : 3;
    extern __shared__ float sm[];
    float* phiS = sm;                      // Ln*Cn*NB  (x only)
    float* Mbuf = sm + Ln * Cn * NB;       // NB*256
    float* vS   = Mbuf + NB * 256;         // NB*16
    const int tid = threadIdx.x;
    const int c = tid;

    // phi precompute (x half only), scattered gathers
    for (int idx = tid; idx < Ln * Cn * NB; idx += 256) {
        int l = idx / (Cn * NB);
        int r = idx - l * (Cn * NB);
        int f = r / NB, b = r - f * NB;
        phiS[idx] = gth(b0 + b, f, p, l);
    }
    for (int i = tid; i < NB * 16; i += 256) vS[i] = 0.25f;  // LB = D^-1/2
    __syncthreads();

    constexpr int OUTS = NB * 16;
    constexpr int KV = (OUTS + 255) / 256;

    for (int l = 0; l < Ln; ++l) {
        const float* W  = cores + (size_t)(p * Ln + l) * (Fn * 256);
        const float* pA = W + c;
        const float* pB = W + Cn * 256 + c;

        float acc[NB];
#pragma unroll
        for (int b = 0; b < NB; ++b) acc[b] = 0.0f;
        float bs0 = 0.f, bs1 = 0.f, bs2 = 0.f, bs3 = 0.f;

        float bufA[PF][4], bufB[PF][4];
#pragma unroll
        for (int g = 0; g < PF; ++g)
#pragma unroll
            for (int i = 0; i < 4; ++i) {
                bufA[g][i] = __ldg(pA + (g * 4 + i) * 256);
                bufB[g][i] = __ldg(pB + (g * 4 + i) * 256);
            }

        const float* ph = phiS + l * Cn * NB;
#pragma unroll
        for (int g = 0; g < Gn; ++g) {
            const int slot = g % PF;
            float wd0 = bufA[slot][0] - bufB[slot][0];
            float wd1 = bufA[slot][1] - bufB[slot][1];
            float wd2 = bufA[slot][2] - bufB[slot][2];
            float wd3 = bufA[slot][3] - bufB[slot][3];
            bs0 += bufB[slot][0]; bs1 += bufB[slot][1];
            bs2 += bufB[slot][2]; bs3 += bufB[slot][3];
            if (g + PF < Gn) {
#pragma unroll
                for (int i = 0; i < 4; ++i) {
                    bufA[slot][i] = __ldg(pA + ((g + PF) * 4 + i) * 256);
                    bufB[slot][i] = __ldg(pB + ((g + PF) * 4 + i) * 256);
                }
            }
#pragma unroll
            for (int q = 0; q < NB; q += 4) {
                float4 x0 = *(const float4*)&ph[(g * 4 + 0) * NB + q];
                float4 x1 = *(const float4*)&ph[(g * 4 + 1) * NB + q];
                float4 x2 = *(const float4*)&ph[(g * 4 + 2) * NB + q];
                float4 x3 = *(const float4*)&ph[(g * 4 + 3) * NB + q];
                acc[q + 0] = fmaf(x0.x, wd0, fmaf(x1.x, wd1, fmaf(x2.x, wd2, fmaf(x3.x, wd3, acc[q + 0]))));
                acc[q + 1] = fmaf(x0.y, wd0, fmaf(x1.y, wd1, fmaf(x2.y, wd2, fmaf(x3.y, wd3, acc[q + 1]))));
                acc[q + 2] = fmaf(x0.z, wd0, fmaf(x1.z, wd1, fmaf(x2.z, wd2, fmaf(x3.z, wd3, acc[q + 2]))));
                acc[q + 3] = fmaf(x0.w, wd0, fmaf(x1.w, wd1, fmaf(x2.w, wd2, fmaf(x3.w, wd3, acc[q + 3]))));
            }
        }
        float bias = (bs0 + bs1) + (bs2 + bs3);
#pragma unroll
        for (int b = 0; b < NB; ++b) Mbuf[b * 256 + c] = acc[b] + bias;
        __syncthreads();   // M visible; vS writes from prev iter visible

        float vnew[KV];
#pragma unroll
        for (int k = 0; k < KV; ++k) {
            int idx = tid + k * 256;
            if (OUTS >= 256 || idx < OUTS) {
                int b = idx >> 4, j = idx & 15;
                float s = 0.0f;
#pragma unroll
                for (int i = 0; i < 16; ++i)
                    s = fmaf(vS[b * 16 + i], Mbuf[b * 256 + i * 16 + j], s);
                vnew[k] = s;
            }
        }
        __syncthreads();   // all scan reads of vS/M done
#pragma unroll
        for (int k = 0; k < KV; ++k) {
            int idx = tid + k * 256;
            if (OUTS >= 256 || idx < OUTS) vS[idx] = vnew[k];
        }
    }
    __syncthreads();
    // Lsum[i,o] = sum_j label[p,i,o,j]  (RB = 0.25 folded at end)
    const float* Lp = label + (size_t)p * (16 * On * 16);
    for (int idx = tid; idx < 16 * On; idx += 256) {
        const float* lp = Lp + idx * 16;
        float s = 0.0f;
#pragma unroll
        for (int j = 0; j < 16; ++j) s += lp[j];
        Mbuf[idx] = s;
    }
    __syncthreads();
    for (int idx = tid; idx < NB * On; idx += 256) {
        int b = idx / On, o = idx - b * On;
        float s = 0.0f;
#pragma unroll
        for (int i = 0; i < 16; ++i)
            s = fmaf(vS[b * 16 + i], Mbuf[i * On + o], s);
        out[(size_t)(b0 + b) * osb + (size_t)p * osp + ooff + o] = 0.25f * s;
    }
}

// ---------------- BatchNorm (training batch stats, in place) ----------------
template <int C, int Lc>
DEV void bn_channel(float* data, const float* g, const float* bet)
{
    constexpr int N = 32 * Lc;
    constexpr int NV = N / 256;
    __shared__ float red[66];
    int ch = blockIdx.x, tid = threadIdx.x;
    float vals[NV];
    float s = 0.0f, s2 = 0.0f;
#pragma unroll
    for (int k = 0; k < NV; ++k) {
        int idx = tid + (k << 8);
        int b = idx / Lc, o = idx % Lc;
        float v = data[(b * C + ch) * Lc + o];
        vals[k] = v; s += v; s2 = fmaf(v, v, s2);
    }
#pragma unroll
    for (int off = 16; off; off >>= 1) {
        s  += __shfl_down_sync(0xffffffffu, s,  off);
        s2 += __shfl_down_sync(0xffffffffu, s2, off);
    }
    int w = tid >> 5, lane = tid & 31;
    if (lane == 0) { red[w] = s; red[33 + w] = s2; }
    __syncthreads();
    if (tid < 32) {
        s  = (lane < 8) ? red[lane] : 0.0f;
        s2 = (lane < 8) ? red[33 + lane] : 0.0f;
#pragma unroll
        for (int off = 4; off; off >>= 1) {
            s  += __shfl_down_sync(0xffffffffu, s,  off);
            s2 += __shfl_down_sync(0xffffffffu, s2, off);
        }
        if (lane == 0) { red[0] = s; red[1] = s2; }
    }
    __syncthreads();
    constexpr float inv = 1.0f / (float)N;
    float mu  = red[0] * inv;
    float var = red[1] * inv - mu * mu;
    float sc = rsqrtf(var + 1e-5f) * g[ch];
    float sh = bet[ch] - mu * sc;
#pragma unroll
    for (int k = 0; k < NV; ++k) {
        int idx = tid + (k << 8);
        int b = idx / Lc, o = idx % Lc;
        data[(b * C + ch) * Lc + o] = fmaf(vals[k], sc, sh);
    }
}

// ---------------- kernels ----------------
__global__ void __launch_bounds__(256)
stage1_kernel(const float* x, const float* l1c, const float* l1l,
              const float* c1c, const float* c1l)
{
    int bi = blockIdx.x;
    if (bi < 512)
        mps_patch<4, 96, 16, 16>(bi >> 1, (bi & 1) << 4, GLote1{x},
                                 l1c, l1l, g_s1l, 4096, 16, 0);
    else {
        bi -= 512;
        mps_patch<3, 32, 16, 16>(bi >> 1, (bi & 1) << 4, GConv1{x},
                                 c1c, c1l, g_s1c, 16384, 16, 0);
    }
}

__global__ void __launch_bounds__(256)
bn_s1l_kernel(const float* g, const float* b) { bn_channel<256, 16>(g_s1l, g, b); }
__global__ void __launch_bounds__(256)
bn_s1c_kernel(const float* g, const float* b) { bn_channel<1024, 16>(g_s1c, g, b); }
__global__ void __launch_bounds__(256)
bn_s2_kernel(const float* g, const float* b) { bn_channel<64, 32>(g_s2, g, b); }
__global__ void __launch_bounds__(256)
bn_s3_kernel(const float* g, const float* b) { bn_channel<16, 32>(g_s3, g, b); }

__global__ void __launch_bounds__(256)
stage2_kernel(const float* l2c, const float* l2l, const float* c2c, const float* c2l)
{
    int bi = blockIdx.x;
    if (bi < 256)
        mps_patch<20, 32, 8, 16>(bi >> 2, (bi & 3) << 3, GComb{g_s1l, g_s1c},
                                 l2c, l2l, g_s2, 2048, 32, 0);
    else {
        bi -= 256;
        mps_patch<16, 40, 8, 16>(bi >> 2, (bi & 3) << 3, GConv2{{g_s1l, g_s1c}},
                                 c2c, c2l, g_s2, 2048, 32, 16);
    }
}

__global__ void __launch_bounds__(256)
stage3_kernel(const float* l3c, const float* l3l, const float* c3c, const float* c3l)
{
    int bi = blockIdx.x;
    if (bi < 128)
        mps_patch<4, 64, 4, 16>(bi >> 3, (bi & 7) << 2, GL3{g_s2},
                                l3c, l3l, g_s3, 512, 32, 0);
    else {
        bi -= 128;
        mps_patch<32, 8, 4, 16>(bi >> 3, (bi & 7) << 2, GC3{g_s2},
                                c3c, c3l, g_s3, 512, 32, 16);
    }
}

__global__ void __launch_bounds__(256)
final_kernel(const float* fc, const float* fl, float* outp)
{
    mps_patch<16, 64, 4, 10>(0, blockIdx.x << 2, GFin{g_s3}, fc, fl, outp, 10, 0, 0);
}

// ---------------- launch ----------------
extern "C" void kernel_launch(void* const* d_in, const int* in_sizes, int n_in,
                              void* d_out, int out_size)
{
    const float* x   = (const float*)d_in[0];
    const float* l1c = (const float*)d_in[1];
    const float* l1l = (const float*)d_in[2];
    const float* c1c = (const float*)d_in[3];
    const float* c1l = (const float*)d_in[4];
    const float* l2c = (const float*)d_in[5];
    const float* l2l = (const float*)d_in[6];
    const float* c2c = (const float*)d_in[7];
    const float* c2l = (const float*)d_in[8];
    const float* l3c = (const float*)d_in[9];
    const float* l3l = (const float*)d_in[10];
    const float* c3c = (const float*)d_in[11];
    const float* c3l = (const float*)d_in[12];
    const float* fc  = (const float*)d_in[13];
    const float* fl  = (const float*)d_in[14];
    const float* g1  = (const float*)d_in[15];
    const float* b1  = (const float*)d_in[16];
    const float* gc1 = (const float*)d_in[17];
    const float* bc1 = (const float*)d_in[18];
    const float* g2  = (const float*)d_in[19];
    const float* b2  = (const float*)d_in[20];
    const float* g3  = (const float*)d_in[21];
    const float* b3  = (const float*)d_in[22];
    float* outp = (float*)d_out;

    // dynamic smem sizes: (phi + M + vS) * 4B
    stage1_kernel<<<2560, 256, (48 * 16 * 4 + 16 * 256 + 16 * 16) * 4>>>(x, l1c, l1l, c1c, c1l);
    bn_s1l_kernel<<<256, 256>>>(g1, b1);
    bn_s1c_kernel<<<1024, 256>>>(gc1, bc1);
    stage2_kernel<<<512, 256, (20 * 8 * 16 + 8 * 256 + 8 * 16) * 4>>>(l2c, l2l, c2c, c2l);
    bn_s2_kernel<<<64, 256>>>(g2, b2);
    stage3_kernel<<<256, 256, (32 * 4 * 4 + 4 * 256 + 4 * 16) * 4>>>(l3c, l3l, c3c, c3l);
    bn_s3_kernel<<<16, 256>>>(g3, b3);
    final_kernel<<<8, 256, (32 * 4 * 16 + 4 * 256 + 4 * 16) * 4>>>(fc, fl, outp);
}

// round 6
// speedup vs baseline: 1.2506x; 1.2506x over previous
#include <cuda_runtime.h>
#include <cuda_bf16.h>

#define DEV __device__ __forceinline__

// ---------------- scratch (static device memory; no allocations) ----------------
__device__ float g_s1l[32 * 256 * 16];   // stage1 LoTe out  [b,256,16]
__device__ float g_s1c[32 * 1024 * 16];  // stage1 Conv out  [b,1024,16]
__device__ float g_s2[32 * 64 * 32];     // stage2 out       [b,64,32]
__device__ float g_s3[32 * 16 * 32];     // stage3 out       [b,16,32]
__device__ float g_M[18874368];          // M scratch (stage2 peak 75.5MB), reused
__device__ float g_Lsum[368800];         // reduced labels, all MPSes

// Lsum segment offsets
#define OFF_L1  0
#define OFF_C1  65536
#define OFF_L2  327680
#define OFF_C2  344064
#define OFF_L3  360448
#define OFF_C3  364544
#define OFF_FIN 368640
// M segment offsets (within-stage)
#define M2C_OFF 10485760
#define M3C_OFF 524288

// ---------------- gathers (exact unfold/reshape index math) ----------------
struct GLote1 {  // a<48,p<256,l<4 from x[b,3,128,128], window 16
    const float* x;
    DEV float operator()(int b, int a, int p, int l) const {
        int flat = a * 1024 + p * 4 + l;
        int c = flat >> 14; int r = flat & 16383;
        int hb = r >> 11; r &= 2047;
        int wb = r >> 8;  r &= 255;
        int h = (hb << 4) + (r >> 4);
        int w = (wb << 4) + (r & 15);
        return x[((b * 3 + c) << 14) + (h << 7) + w];
    }
};
struct GConv1 {  // a<16,p<1024,l<3, window 4
    const float* x;
    DEV float operator()(int b, int a, int p, int l) const {
        int flat = a * 3072 + p * 3 + l;
        int c = flat >> 14; int r = flat & 16383;
        int hb = r >> 9; r &= 511;
        int wb = r >> 4; r &= 15;
        int h = (hb << 2) + (r >> 2);
        int w = (wb << 2) + (r & 3);
        return x[((b * 3 + c) << 14) + (h << 7) + w];
    }
};
struct GComb {   // comb[b,a,p,l]: a<16,p<64,l<20
    const float* ly;
    const float* cy;
    DEV float operator()(int b, int a, int p, int l) const {
        if (l < 4) {
            int r = (p << 2) + l;
            int hb = r >> 7; r &= 127;
            int wb = r >> 6; r &= 63;
            int h = (hb << 3) + (r >> 3);
            int w = (wb << 3) + (r & 7);
            return ly[(b * 256 + (a << 4) + h) * 16 + w];
        } else {
            int a2 = l - 4, l2 = a;
            int r = (p << 4) + l2;
            int hb = r >> 7; r &= 127;
            int wb = r >> 4; r &= 15;
            int h = (hb << 2) + (r >> 2);
            int w = (wb << 2) + (r & 3);
            int f3 = (a2 << 10) + (h << 5) + w;
            return cy[(b * 1024 + (f3 >> 4)) * 16 + (f3 & 15)];
        }
    }
};
struct GConv2 {
    GComb inner;
    DEV float operator()(int b, int a, int p, int l) const { return inner(b, l, p, a); }
};
struct GL3 {     // a<32,p<16,l<4 from grid[b,32,8,8]
    const float* s2;
    DEV float operator()(int b, int a, int p, int l) const {
        int r = (p << 2) + l;
        int hb = r >> 5; r &= 31;
        int wb = r >> 4; r &= 15;
        int h = (hb << 2) + (r >> 2);
        int w = (wb << 2) + (r & 3);
        int f3 = (a << 6) + (h << 3) + w;
        return s2[((b << 6) + (f3 >> 5)) * 32 + (f3 & 31)];
    }
};
struct GC3 {     // a<4,p<16,l<32, window 2
    const float* s2;
    DEV float operator()(int b, int a, int p, int l) const {
        int flat = (a << 9) + (p << 5) + l;
        int c = flat >> 6; int r = flat & 63;
        int hb = r >> 4; r &= 15;
        int wb = r >> 2; r &= 3;
        int h = (hb << 1) + (r >> 1);
        int w = (wb << 1) + (r & 1);
        int f3 = (c << 6) + (h << 3) + w;
        return s2[((b << 6) + (f3 >> 5)) * 32 + (f3 & 31)];
    }
};
struct GFin {    // a<32,l<16
    const float* s3;
    DEV float operator()(int b, int a, int /*p*/, int l) const {
        return s3[(((b << 4) + l) << 5) + a];
    }
};

// ---------------- label pre-reduction ----------------
__global__ void __launch_bounds__(256)
lsum_k(const float* __restrict__ lab, float* __restrict__ dst, int n)
{
    int i = blockIdx.x * 256 + threadIdx.x;
    if (i >= n) return;
    const float4* lp = (const float4*)(lab + (size_t)i * 16);
    float4 a = lp[0], b = lp[1], c = lp[2], d = lp[3];
    dst[i] = ((a.x + a.y) + (a.z + a.w)) + ((b.x + b.y) + (b.z + b.w)) +
             ((c.x + c.y) + (c.z + c.w)) + ((d.x + d.y) + (d.z + d.w));
}

// ---------------- stage1: fused chunked MPS (NB=16, chunk=2 l's) ----------------
// phi-fold: M = sum_f x_f*(W_f - W_{f+Cn}) + sum_f W_{f+Cn}
template <int Ln, int Fn, int NB, typename G>
DEV void mps_fused(int p, int b0, const G& gth,
                   const float* __restrict__ cores,
                   const float* __restrict__ Lsum,
                   float* __restrict__ out, int osb, int osp)
{
    constexpr int Cn = Fn / 2;
    __shared__ float phiS[Ln * Cn * NB];
    __shared__ float Mbuf[2 * NB * 256];
    const int tid = threadIdx.x;
    const int c = tid;

    for (int idx = tid; idx < Ln * Cn * NB; idx += 256) {
        int l = idx / (Cn * NB);
        int r = idx - l * (Cn * NB);
        int f = r / NB, b = r - f * NB;
        phiS[idx] = gth(b0 + b, f, p, l);
    }
    __syncthreads();

    const int lane = tid & 31;
    const int bb = tid >> 4;    // chain (batch) index within slice, 0..15
    const int j  = tid & 15;
    float v = 0.25f;            // LB = D^-1/2

    for (int l0 = 0; l0 < Ln; l0 += 2) {
        const int nl = (Ln - l0 < 2) ? (Ln - l0) : 2;
#pragma unroll
        for (int lc = 0; lc < 2; ++lc) {
            if (lc >= nl) break;
            const float* Wl = cores + (size_t)(p * Ln + l0 + lc) * (Fn * 256) + c;
            const float* ph = phiS + (l0 + lc) * Cn * NB;
            float acc[NB];
#pragma unroll
            for (int b = 0; b < NB; ++b) acc[b] = 0.0f;
            float bias = 0.0f;
#pragma unroll 8
            for (int f = 0; f < Cn; ++f) {
                float wa = __ldg(Wl + f * 256);
                float wb = __ldg(Wl + (f + Cn) * 256);
                float wd = wa - wb; bias += wb;
#pragma unroll
                for (int q = 0; q < NB; q += 4) {
                    float4 xv = *(const float4*)&ph[f * NB + q];
                    acc[q + 0] = fmaf(xv.x, wd, acc[q + 0]);
                    acc[q + 1] = fmaf(xv.y, wd, acc[q + 1]);
                    acc[q + 2] = fmaf(xv.z, wd, acc[q + 2]);
                    acc[q + 3] = fmaf(xv.w, wd, acc[q + 3]);
                }
            }
#pragma unroll
            for (int b = 0; b < NB; ++b) Mbuf[(lc * NB + b) * 256 + c] = acc[b] + bias;
        }
        __syncthreads();
        for (int lc = 0; lc < nl; ++lc) {
            const float* Mb = Mbuf + (lc * NB + bb) * 256 + j;
            float s = 0.0f;
#pragma unroll
            for (int i = 0; i < 16; ++i) {
                float vi = __shfl_sync(0xffffffffu, v, (lane & 16) | i, 32);
                s = fmaf(vi, Mb[i * 16], s);
            }
            v = s;
        }
        __syncthreads();
    }
    const float* Ls = Lsum + p * 256;
    float s = 0.0f;
#pragma unroll
    for (int i = 0; i < 16; ++i) {
        float vi = __shfl_sync(0xffffffffu, v, (lane & 16) | i, 32);
        s = fmaf(vi, __ldg(Ls + i * 16 + j), s);
    }
    out[(size_t)(b0 + bb) * osb + (size_t)p * osp + j] = 0.25f * s;
}

__global__ void __launch_bounds__(256)
s1_lote_k(const float* __restrict__ x, const float* __restrict__ cores)
{
    int bi = blockIdx.x;   // 512
    mps_fused<4, 96, 16>(bi >> 1, (bi & 1) << 4, GLote1{x}, cores,
                         g_Lsum + OFF_L1, g_s1l, 4096, 16);
}
__global__ void __launch_bounds__(256)
s1_conv_k(const float* __restrict__ x, const float* __restrict__ cores)
{
    int bi = blockIdx.x;   // 2048
    mps_fused<3, 32, 16>(bi >> 1, (bi & 1) << 4, GConv1{x}, cores,
                         g_Lsum + OFF_C1, g_s1c, 16384, 16);
}

// ---------------- kernel A body: per-(p,l) GEMM, NB=32, pure weight stream ----------------
template <int Ln, int Fn, typename G>
DEV void kernelA_body(const G& gth, const float* __restrict__ cores,
                      float* __restrict__ Mg)
{
    constexpr int Cn = Fn / 2;
    __shared__ float phiS[Cn * 32];
    const int blk = blockIdx.x;
    const int p = blk / Ln, l = blk - p * Ln;
    const int tid = threadIdx.x;
    const int c = tid;
    for (int idx = tid; idx < Cn * 32; idx += 256) {
        int f = idx >> 5, b = idx & 31;
        phiS[idx] = gth(b, f, p, l);
    }
    __syncthreads();
    const float* Wl = cores + (size_t)blk * (Fn * 256) + c;
    float acc[32];
#pragma unroll
    for (int b = 0; b < 32; ++b) acc[b] = 0.0f;
    float bias = 0.0f;
#pragma unroll 8
    for (int f = 0; f < Cn; ++f) {
        float wa = __ldg(Wl + f * 256);
        float wb = __ldg(Wl + (f + Cn) * 256);
        float wd = wa - wb; bias += wb;
#pragma unroll
        for (int q = 0; q < 32; q += 4) {
            float4 xv = *(const float4*)&phiS[f * 32 + q];
            acc[q + 0] = fmaf(xv.x, wd, acc[q + 0]);
            acc[q + 1] = fmaf(xv.y, wd, acc[q + 1]);
            acc[q + 2] = fmaf(xv.z, wd, acc[q + 2]);
            acc[q + 3] = fmaf(xv.w, wd, acc[q + 3]);
        }
    }
    float* Mo = Mg + (size_t)blk * (32 * 256) + c;
#pragma unroll
    for (int b = 0; b < 32; ++b) Mo[b * 256] = acc[b] + bias;
}

// wrappers: functors constructed IN DEVICE CODE (device symbol addresses)
__global__ void __launch_bounds__(256)
a2l_k(const float* __restrict__ cores) {
    kernelA_body<20, 32>(GComb{g_s1l, g_s1c}, cores, g_M);
}
__global__ void __launch_bounds__(256)
a2c_k(const float* __restrict__ cores) {
    kernelA_body<16, 40>(GConv2{{g_s1l, g_s1c}}, cores, g_M + M2C_OFF);
}
__global__ void __launch_bounds__(256)
a3l_k(const float* __restrict__ cores) {
    kernelA_body<4, 64>(GL3{g_s2}, cores, g_M);
}
__global__ void __launch_bounds__(256)
a3c_k(const float* __restrict__ cores) {
    kernelA_body<32, 8>(GC3{g_s2}, cores, g_M + M3C_OFF);
}
__global__ void __launch_bounds__(256)
afin_k(const float* __restrict__ cores) {
    kernelA_body<16, 64>(GFin{g_s3}, cores, g_M);
}

// ---------------- kernel B: scan over global M + label ----------------
template <int Ln, int On>
DEV void kernelB_body(const float* __restrict__ Mg, const float* __restrict__ Lsum,
                      float* __restrict__ out, int osb, int osp, int ooff)
{
    const int tid = threadIdx.x, lane = tid & 31;
    const int chain = blockIdx.x * 16 + (tid >> 4);
    const int p = chain >> 5, b = chain & 31;
    const int j = tid & 15;
    float v = 0.25f;
    const float* Mb = Mg + ((size_t)(p * Ln) * 32 + b) * 256 + j;
    for (int l = 0; l < Ln; ++l) {
        float s = 0.0f;
#pragma unroll
        for (int i = 0; i < 16; ++i) {
            float vi = __shfl_sync(0xffffffffu, v, (lane & 16) | i, 32);
            s = fmaf(vi, __ldg(Mb + i * 16), s);
        }
        v = s;
        Mb += 32 * 256;
    }
    float s = 0.0f;
    const float* Ls = Lsum + p * 16 * On;
#pragma unroll
    for (int i = 0; i < 16; ++i) {
        float vi = __shfl_sync(0xffffffffu, v, (lane & 16) | i, 32);
        float lv = (j < On) ? __ldg(Ls + i * On + j) : 0.0f;
        s = fmaf(vi, lv, s);
    }
    if (j < On)
        out[(size_t)b * osb + (size_t)p * osp + ooff + j] = 0.25f * s;
}

__global__ void __launch_bounds__(256)
b2l_k() { kernelB_body<20, 16>(g_M, g_Lsum + OFF_L2, g_s2, 2048, 32, 0); }
__global__ void __launch_bounds__(256)
b2c_k() { kernelB_body<16, 16>(g_M + M2C_OFF, g_Lsum + OFF_C2, g_s2, 2048, 32, 16); }
__global__ void __launch_bounds__(256)
b3l_k() { kernelB_body<4, 16>(g_M, g_Lsum + OFF_L3, g_s3, 512, 32, 0); }
__global__ void __launch_bounds__(256)
b3c_k() { kernelB_body<32, 16>(g_M + M3C_OFF, g_Lsum + OFF_C3, g_s3, 512, 32, 16); }
__global__ void __launch_bounds__(256)
bfin_k(float* __restrict__ outp) { kernelB_body<16, 10>(g_M, g_Lsum + OFF_FIN, outp, 10, 0, 0); }

// ---------------- BatchNorm (training batch stats, in place) ----------------
template <int C, int Lc>
DEV void bn_channel(float* data, const float* g, const float* bet)
{
    constexpr int N = 32 * Lc;
    constexpr int NV = N / 256;
    __shared__ float red[66];
    int ch = blockIdx.x, tid = threadIdx.x;
    float vals[NV];
    float s = 0.0f, s2 = 0.0f;
#pragma unroll
    for (int k = 0; k < NV; ++k) {
        int idx = tid + (k << 8);
        int b = idx / Lc, o = idx % Lc;
        float v = data[(b * C + ch) * Lc + o];
        vals[k] = v; s += v; s2 = fmaf(v, v, s2);
    }
#pragma unroll
    for (int off = 16; off; off >>= 1) {
        s  += __shfl_down_sync(0xffffffffu, s,  off);
        s2 += __shfl_down_sync(0xffffffffu, s2, off);
    }
    int w = tid >> 5, lane = tid & 31;
    if (lane == 0) { red[w] = s; red[33 + w] = s2; }
    __syncthreads();
    if (tid < 32) {
        s  = (lane < 8) ? red[lane] : 0.0f;
        s2 = (lane < 8) ? red[33 + lane] : 0.0f;
#pragma unroll
        for (int off = 4; off; off >>= 1) {
            s  += __shfl_down_sync(0xffffffffu, s,  off);
            s2 += __shfl_down_sync(0xffffffffu, s2, off);
        }
        if (lane == 0) { red[0] = s; red[1] = s2; }
    }
    __syncthreads();
    constexpr float inv = 1.0f / (float)N;
    float mu  = red[0] * inv;
    float var = red[1] * inv - mu * mu;
    float sc = rsqrtf(var + 1e-5f) * g[ch];
    float sh = bet[ch] - mu * sc;
#pragma unroll
    for (int k = 0; k < NV; ++k) {
        int idx = tid + (k << 8);
        int b = idx / Lc, o = idx % Lc;
        data[(b * C + ch) * Lc + o] = fmaf(vals[k], sc, sh);
    }
}

__global__ void __launch_bounds__(256)
bn_s1l_kernel(const float* g, const float* b) { bn_channel<256, 16>(g_s1l, g, b); }
__global__ void __launch_bounds__(256)
bn_s1c_kernel(const float* g, const float* b) { bn_channel<1024, 16>(g_s1c, g, b); }
__global__ void __launch_bounds__(256)
bn_s2_kernel(const float* g, const float* b) { bn_channel<64, 32>(g_s2, g, b); }
__global__ void __launch_bounds__(256)
bn_s3_kernel(const float* g, const float* b) { bn_channel<16, 32>(g_s3, g, b); }

// ---------------- launch ----------------
extern "C" void kernel_launch(void* const* d_in, const int* in_sizes, int n_in,
                              void* d_out, int out_size)
{
    const float* x   = (const float*)d_in[0];
    const float* l1c = (const float*)d_in[1];
    const float* l1l = (const float*)d_in[2];
    const float* c1c = (const float*)d_in[3];
    const float* c1l = (const float*)d_in[4];
    const float* l2c = (const float*)d_in[5];
    const float* l2l = (const float*)d_in[6];
    const float* c2c = (const float*)d_in[7];
    const float* c2l = (const float*)d_in[8];
    const float* l3c = (const float*)d_in[9];
    const float* l3l = (const float*)d_in[10];
    const float* c3c = (const float*)d_in[11];
    const float* c3l = (const float*)d_in[12];
    const float* fc  = (const float*)d_in[13];
    const float* fl  = (const float*)d_in[14];
    const float* g1  = (const float*)d_in[15];
    const float* b1  = (const float*)d_in[16];
    const float* gc1 = (const float*)d_in[17];
    const float* bc1 = (const float*)d_in[18];
    const float* g2  = (const float*)d_in[19];
    const float* b2  = (const float*)d_in[20];
    const float* g3  = (const float*)d_in[21];
    const float* b3  = (const float*)d_in[22];
    float* outp = (float*)d_out;

    float* Lb = nullptr;
    cudaGetSymbolAddress((void**)&Lb, g_Lsum);

    // label pre-reduction
    lsum_k<<<256, 256>>>(l1l, Lb + OFF_L1, 65536);
    lsum_k<<<1024, 256>>>(c1l, Lb + OFF_C1, 262144);
    lsum_k<<<64, 256>>>(l2l, Lb + OFF_L2, 16384);
    lsum_k<<<64, 256>>>(c2l, Lb + OFF_C2, 16384);
    lsum_k<<<16, 256>>>(l3l, Lb + OFF_L3, 4096);
    lsum_k<<<16, 256>>>(c3l, Lb + OFF_C3, 4096);
    lsum_k<<<1, 256>>>(fl, Lb + OFF_FIN, 160);

    // stage 1 (fused)
    s1_lote_k<<<512, 256>>>(x, l1c);
    s1_conv_k<<<2048, 256>>>(x, c1c);
    bn_s1l_kernel<<<256, 256>>>(g1, b1);
    bn_s1c_kernel<<<1024, 256>>>(gc1, bc1);

    // stage 2 (split)
    a2l_k<<<1280, 256>>>(l2c);
    a2c_k<<<1024, 256>>>(c2c);
    b2l_k<<<128, 256>>>();
    b2c_k<<<128, 256>>>();
    bn_s2_kernel<<<64, 256>>>(g2, b2);

    // stage 3 (split)
    a3l_k<<<64, 256>>>(l3c);
    a3c_k<<<512, 256>>>(c3c);
    b3l_k<<<32, 256>>>();
    b3c_k<<<32, 256>>>();
    bn_s3_kernel<<<16, 256>>>(g3, b3);

    // final (split)
    afin_k<<<16, 256>>>(fc);
    bfin_k<<<2, 256>>>(outp);
}

// round 8
// speedup vs baseline: 1.6511x; 1.3202x over previous
#include <cuda_runtime.h>
#include <cuda_bf16.h>

#define DEV __device__ __forceinline__

// ---------------- scratch (static device memory; no allocations) ----------------
__device__ float g_s1l[32 * 256 * 16];   // stage1 LoTe out  [b,256,16]
__device__ float g_s1c[32 * 1024 * 16];  // stage1 Conv out  [b,1024,16]
__device__ float g_s2[32 * 64 * 32];     // stage2 out       [b,64,32]
__device__ float g_s3[32 * 16 * 32];     // stage3 out       [b,16,32]
__device__ float g_M[18874368];          // M scratch (stage2 peak 75.5MB), reused
__device__ float g_Lsum[368800];         // reduced labels, all MPSes

// Lsum segment offsets
#define OFF_L1  0
#define OFF_C1  65536
#define OFF_L2  327680
#define OFF_C2  344064
#define OFF_L3  360448
#define OFF_C3  364544
#define OFF_FIN 368640
// M segment offsets (within-stage)
#define M2C_OFF 10485760
#define M3C_OFF 524288

// ---------------- gathers (exact unfold/reshape index math) ----------------
struct GLote1 {  // a<48,p<256,l<4 from x[b,3,128,128], window 16
    const float* x;
    DEV float operator()(int b, int a, int p, int l) const {
        int flat = a * 1024 + p * 4 + l;
        int c = flat >> 14; int r = flat & 16383;
        int hb = r >> 11; r &= 2047;
        int wb = r >> 8;  r &= 255;
        int h = (hb << 4) + (r >> 4);
        int w = (wb << 4) + (r & 15);
        return x[((b * 3 + c) << 14) + (h << 7) + w];
    }
};
struct GConv1 {  // a<16,p<1024,l<3, window 4
    const float* x;
    DEV float operator()(int b, int a, int p, int l) const {
        int flat = a * 3072 + p * 3 + l;
        int c = flat >> 14; int r = flat & 16383;
        int hb = r >> 9; r &= 511;
        int wb = r >> 4; r &= 15;
        int h = (hb << 2) + (r >> 2);
        int w = (wb << 2) + (r & 3);
        return x[((b * 3 + c) << 14) + (h << 7) + w];
    }
};
struct GComb {   // comb[b,a,p,l]: a<16,p<64,l<20
    const float* ly;
    const float* cy;
    DEV float operator()(int b, int a, int p, int l) const {
        if (l < 4) {
            int r = (p << 2) + l;
            int hb = r >> 7; r &= 127;
            int wb = r >> 6; r &= 63;
            int h = (hb << 3) + (r >> 3);
            int w = (wb << 3) + (r & 7);
            return ly[(b * 256 + (a << 4) + h) * 16 + w];
        } else {
            int a2 = l - 4, l2 = a;
            int r = (p << 4) + l2;
            int hb = r >> 7; r &= 127;
            int wb = r >> 4; r &= 15;
            int h = (hb << 2) + (r >> 2);
            int w = (wb << 2) + (r & 3);
            int f3 = (a2 << 10) + (h << 5) + w;
            return cy[(b * 1024 + (f3 >> 4)) * 16 + (f3 & 15)];
        }
    }
};
struct GConv2 {
    GComb inner;
    DEV float operator()(int b, int a, int p, int l) const { return inner(b, l, p, a); }
};
struct GL3 {     // a<32,p<16,l<4 from grid[b,32,8,8]
    const float* s2;
    DEV float operator()(int b, int a, int p, int l) const {
        int r = (p << 2) + l;
        int hb = r >> 5; r &= 31;
        int wb = r >> 4; r &= 15;
        int h = (hb << 2) + (r >> 2);
        int w = (wb << 2) + (r & 3);
        int f3 = (a << 6) + (h << 3) + w;
        return s2[((b << 6) + (f3 >> 5)) * 32 + (f3 & 31)];
    }
};
struct GC3 {     // a<4,p<16,l<32, window 2
    const float* s2;
    DEV float operator()(int b, int a, int p, int l) const {
        int flat = (a << 9) + (p << 5) + l;
        int c = flat >> 6; int r = flat & 63;
        int hb = r >> 4; r &= 15;
        int wb = r >> 2; r &= 3;
        int h = (hb << 1) + (r >> 1);
        int w = (wb << 1) + (r & 1);
        int f3 = (c << 6) + (h << 3) + w;
        return s2[((b << 6) + (f3 >> 5)) * 32 + (f3 & 31)];
    }
};
struct GFin {    // a<32,l<16
    const float* s3;
    DEV float operator()(int b, int a, int /*p*/, int l) const {
        return s3[(((b << 4) + l) << 5) + a];
    }
};

// ---------------- label pre-reduction ----------------
DEV void lsum_body(const float* __restrict__ lab, float* __restrict__ dst, int i, int n)
{
    if (i >= n) return;
    const float4* lp = (const float4*)(lab + (size_t)i * 16);
    float4 a = lp[0], b = lp[1], c = lp[2], d = lp[3];
    dst[i] = ((a.x + a.y) + (a.z + a.w)) + ((b.x + b.y) + (b.z + b.w)) +
             ((c.x + c.y) + (c.z + c.w)) + ((d.x + d.y) + (d.z + d.w));
}
__global__ void __launch_bounds__(256)
lsumA_k(const float* __restrict__ c1l)   // 1024 blocks
{
    lsum_body(c1l, g_Lsum + OFF_C1, blockIdx.x * 256 + threadIdx.x, 262144);
}
__global__ void __launch_bounds__(256)
lsumB_k(const float* __restrict__ l1l, const float* __restrict__ l2l,
        const float* __restrict__ c2l, const float* __restrict__ l3l,
        const float* __restrict__ c3l, const float* __restrict__ fl)  // 417 blocks
{
    int bi = blockIdx.x, t = threadIdx.x;
    if (bi < 256)      lsum_body(l1l, g_Lsum + OFF_L1, bi * 256 + t, 65536);
    else if (bi < 320) lsum_body(l2l, g_Lsum + OFF_L2, (bi - 256) * 256 + t, 16384);
    else if (bi < 384) lsum_body(c2l, g_Lsum + OFF_C2, (bi - 320) * 256 + t, 16384);
    else if (bi < 400) lsum_body(l3l, g_Lsum + OFF_L3, (bi - 384) * 256 + t, 4096);
    else if (bi < 416) lsum_body(c3l, g_Lsum + OFF_C3, (bi - 400) * 256 + t, 4096);
    else               lsum_body(fl,  g_Lsum + OFF_FIN, t, 160);
}

// ---------------- stage1: fused MPS, full batch NB=32 per CTA ----------------
// phi-fold: M = sum_f x_f*(W_f - W_{f+Cn}) + sum_f W_{f+Cn}
// Each thread owns M column c for all 32 b; scan holds two chains (b, b+16)
// in registers via 16-lane shuffles. 2 barriers per 2-l chunk.
template <int Ln, int Fn, typename G>
DEV void mps_fused32(int p, const G& gth, const float* __restrict__ cores,
                     const float* __restrict__ Lsum, float* __restrict__ out,
                     int osb, int osp)
{
    constexpr int Cn = Fn / 2;
    extern __shared__ float sm[];
    float* phiS = sm;                  // Ln*Cn*32
    float* Mbuf = sm + Ln * Cn * 32;   // 2*32*256
    const int tid = threadIdx.x, c = tid, lane = tid & 31;
    const int bb = tid >> 4, j = tid & 15;

    for (int idx = tid; idx < Ln * Cn * 32; idx += 256) {
        int l = idx / (Cn * 32);
        int r = idx - l * (Cn * 32);
        phiS[idx] = gth(r & 31, r >> 5, p, l);
    }
    __syncthreads();

    float v0 = 0.25f, v1 = 0.25f;      // LB = D^-1/2

    for (int l0 = 0; l0 < Ln; l0 += 2) {
        const int nl = (Ln - l0 < 2) ? (Ln - l0) : 2;
#pragma unroll
        for (int lc = 0; lc < 2; ++lc) {
            if (lc >= nl) break;
            const float* Wl = cores + (size_t)(p * Ln + l0 + lc) * (Fn * 256) + c;
            const float* ph = phiS + (l0 + lc) * Cn * 32;
            float acc[32];
#pragma unroll
            for (int b = 0; b < 32; ++b) acc[b] = 0.0f;
            float bias = 0.0f;
#pragma unroll 8
            for (int f = 0; f < Cn; ++f) {
                float wa = __ldg(Wl + f * 256);
                float wb = __ldg(Wl + (f + Cn) * 256);
                float wd = wa - wb; bias += wb;
#pragma unroll
                for (int q = 0; q < 32; q += 4) {
                    float4 xv = *(const float4*)&ph[f * 32 + q];
                    acc[q + 0] = fmaf(xv.x, wd, acc[q + 0]);
                    acc[q + 1] = fmaf(xv.y, wd, acc[q + 1]);
                    acc[q + 2] = fmaf(xv.z, wd, acc[q + 2]);
                    acc[q + 3] = fmaf(xv.w, wd, acc[q + 3]);
                }
            }
#pragma unroll
            for (int b = 0; b < 32; ++b) Mbuf[(lc * 32 + b) * 256 + c] = acc[b] + bias;
        }
        __syncthreads();
        for (int lc = 0; lc < nl; ++lc) {
            const float* M0 = Mbuf + (lc * 32 + bb) * 256 + j;
            const float* M1 = Mbuf + (lc * 32 + 16 + bb) * 256 + j;
            float s0 = 0.0f, s1 = 0.0f;
#pragma unroll
            for (int i = 0; i < 16; ++i) {
                float a0 = __shfl_sync(0xffffffffu, v0, (lane & 16) | i, 32);
                float a1 = __shfl_sync(0xffffffffu, v1, (lane & 16) | i, 32);
                s0 = fmaf(a0, M0[i * 16], s0);
                s1 = fmaf(a1, M1[i * 16], s1);
            }
            v0 = s0; v1 = s1;
        }
        __syncthreads();
    }
    const float* Ls = Lsum + p * 256;
    float s0 = 0.0f, s1 = 0.0f;
#pragma unroll
    for (int i = 0; i < 16; ++i) {
        float a0 = __shfl_sync(0xffffffffu, v0, (lane & 16) | i, 32);
        float a1 = __shfl_sync(0xffffffffu, v1, (lane & 16) | i, 32);
        float lv = __ldg(Ls + i * 16 + j);
        s0 = fmaf(a0, lv, s0);
        s1 = fmaf(a1, lv, s1);
    }
    out[(size_t)bb * osb + (size_t)p * osp + j] = 0.25f * s0;
    out[(size_t)(16 + bb) * osb + (size_t)p * osp + j] = 0.25f * s1;
}

__global__ void __launch_bounds__(256)
s1_k(const float* __restrict__ x, const float* __restrict__ l1c,
     const float* __restrict__ c1c)
{
    int bi = blockIdx.x;   // 0..255 lote, 256..1279 conv
    if (bi < 256)
        mps_fused32<4, 96>(bi, GLote1{x}, l1c, g_Lsum + OFF_L1, g_s1l, 4096, 16);
    else
        mps_fused32<3, 32>(bi - 256, GConv1{x}, c1c, g_Lsum + OFF_C1, g_s1c, 16384, 16);
}

// ---------------- kernel A body: per-(p,l) GEMM, NB=32, pure weight stream ----------------
template <int Ln, int Fn, typename G>
DEV void kernelA_body(int blk, const G& gth, const float* __restrict__ cores,
                      float* __restrict__ Mg)
{
    constexpr int Cn = Fn / 2;
    __shared__ float phiS[Cn * 32];
    const int p = blk / Ln, l = blk - p * Ln;
    const int tid = threadIdx.x;
    const int c = tid;
    for (int idx = tid; idx < Cn * 32; idx += 256) {
        int f = idx >> 5, b = idx & 31;
        phiS[idx] = gth(b, f, p, l);
    }
    __syncthreads();
    const float* Wl = cores + (size_t)blk * (Fn * 256) + c;
    float acc[32];
#pragma unroll
    for (int b = 0; b < 32; ++b) acc[b] = 0.0f;
    float bias = 0.0f;
#pragma unroll 8
    for (int f = 0; f < Cn; ++f) {
        float wa = __ldg(Wl + f * 256);
        float wb = __ldg(Wl + (f + Cn) * 256);
        float wd = wa - wb; bias += wb;
#pragma unroll
        for (int q = 0; q < 32; q += 4) {
            float4 xv = *(const float4*)&phiS[f * 32 + q];
            acc[q + 0] = fmaf(xv.x, wd, acc[q + 0]);
            acc[q + 1] = fmaf(xv.y, wd, acc[q + 1]);
            acc[q + 2] = fmaf(xv.z, wd, acc[q + 2]);
            acc[q + 3] = fmaf(xv.w, wd, acc[q + 3]);
        }
    }
    float* Mo = Mg + (size_t)blk * (32 * 256) + c;
#pragma unroll
    for (int b = 0; b < 32; ++b) Mo[b * 256] = acc[b] + bias;
}

__global__ void __launch_bounds__(256)
a2_k(const float* __restrict__ l2c, const float* __restrict__ c2c)  // 2304 blocks
{
    int bi = blockIdx.x;
    if (bi < 1280)
        kernelA_body<20, 32>(bi, GComb{g_s1l, g_s1c}, l2c, g_M);
    else
        kernelA_body<16, 40>(bi - 1280, GConv2{{g_s1l, g_s1c}}, c2c, g_M + M2C_OFF);
}
__global__ void __launch_bounds__(256)
a3_k(const float* __restrict__ l3c, const float* __restrict__ c3c)  // 576 blocks
{
    int bi = blockIdx.x;
    if (bi < 64)
        kernelA_body<4, 64>(bi, GL3{g_s2}, l3c, g_M);
    else
        kernelA_body<32, 8>(bi - 64, GC3{g_s2}, c3c, g_M + M3C_OFF);
}
__global__ void __launch_bounds__(256)
afin_k(const float* __restrict__ fc)    // 16 blocks
{
    kernelA_body<16, 64>(blockIdx.x, GFin{g_s3}, fc, g_M);
}

// ---------------- kernel B: scan over global M + label ----------------
template <int Ln, int On>
DEV void kernelB_body(int blk, const float* __restrict__ Mg,
                      const float* __restrict__ Lsum,
                      float* __restrict__ out, int osb, int osp, int ooff)
{
    const int tid = threadIdx.x, lane = tid & 31;
    const int chain = blk * 16 + (tid >> 4);
    const int p = chain >> 5, b = chain & 31;
    const int j = tid & 15;
    float v = 0.25f;
    const float* Mb = Mg + ((size_t)(p * Ln) * 32 + b) * 256 + j;
    for (int l = 0; l < Ln; ++l) {
        float s = 0.0f;
#pragma unroll
        for (int i = 0; i < 16; ++i) {
            float vi = __shfl_sync(0xffffffffu, v, (lane & 16) | i, 32);
            s = fmaf(vi, __ldg(Mb + i * 16), s);
        }
        v = s;
        Mb += 32 * 256;
    }
    float s = 0.0f;
    const float* Ls = Lsum + p * 16 * On;
#pragma unroll
    for (int i = 0; i < 16; ++i) {
        float vi = __shfl_sync(0xffffffffu, v, (lane & 16) | i, 32);
        float lv = (j < On) ? __ldg(Ls + i * On + j) : 0.0f;
        s = fmaf(vi, lv, s);
    }
    if (j < On)
        out[(size_t)b * osb + (size_t)p * osp + ooff + j] = 0.25f * s;
}

__global__ void __launch_bounds__(256)
b2_k()  // 256 blocks: 0..127 lote, 128..255 conv
{
    int bi = blockIdx.x;
    if (bi < 128) kernelB_body<20, 16>(bi, g_M, g_Lsum + OFF_L2, g_s2, 2048, 32, 0);
    else          kernelB_body<16, 16>(bi - 128, g_M + M2C_OFF, g_Lsum + OFF_C2, g_s2, 2048, 32, 16);
}
__global__ void __launch_bounds__(256)
b3_k()  // 64 blocks
{
    int bi = blockIdx.x;
    if (bi < 32) kernelB_body<4, 16>(bi, g_M, g_Lsum + OFF_L3, g_s3, 512, 32, 0);
    else         kernelB_body<32, 16>(bi - 32, g_M + M3C_OFF, g_Lsum + OFF_C3, g_s3, 512, 32, 16);
}
__global__ void __launch_bounds__(256)
bfin_k(float* __restrict__ outp)  // 2 blocks
{
    kernelB_body<16, 10>(blockIdx.x, g_M, g_Lsum + OFF_FIN, outp, 10, 0, 0);
}

// ---------------- BatchNorm (training batch stats, in place) ----------------
template <int C, int Lc>
DEV void bn_channel(float* data, const float* g, const float* bet)
{
    constexpr int N = 32 * Lc;
    constexpr int NV = N / 256;
    __shared__ float red[66];
    int ch = blockIdx.x, tid = threadIdx.x;
    float vals[NV];
    float s = 0.0f, s2 = 0.0f;
#pragma unroll
    for (int k = 0; k < NV; ++k) {
        int idx = tid + (k << 8);
        int b = idx / Lc, o = idx % Lc;
        float v = data[(b * C + ch) * Lc + o];
        vals[k] = v; s += v; s2 = fmaf(v, v, s2);
    }
#pragma unroll
    for (int off = 16; off; off >>= 1) {
        s  += __shfl_down_sync(0xffffffffu, s,  off);
        s2 += __shfl_down_sync(0xffffffffu, s2, off);
    }
    int w = tid >> 5, lane = tid & 31;
    if (lane == 0) { red[w] = s; red[33 + w] = s2; }
    __syncthreads();
    if (tid < 32) {
        s  = (lane < 8) ? red[lane] : 0.0f;
        s2 = (lane < 8) ? red[33 + lane] : 0.0f;
#pragma unroll
        for (int off = 4; off; off >>= 1) {
            s  += __shfl_down_sync(0xffffffffu, s,  off);
            s2 += __shfl_down_sync(0xffffffffu, s2, off);
        }
        if (lane == 0) { red[0] = s; red[1] = s2; }
    }
    __syncthreads();
    constexpr float inv = 1.0f / (float)N;
    float mu  = red[0] * inv;
    float var = red[1] * inv - mu * mu;
    float sc = rsqrtf(var + 1e-5f) * g[ch];
    float sh = bet[ch] - mu * sc;
#pragma unroll
    for (int k = 0; k < NV; ++k) {
        int idx = tid + (k << 8);
        int b = idx / Lc, o = idx % Lc;
        data[(b * C + ch) * Lc + o] = fmaf(vals[k], sc, sh);
    }
}

__global__ void __launch_bounds__(256)
bn_s1l_kernel(const float* g, const float* b) { bn_channel<256, 16>(g_s1l, g, b); }
__global__ void __launch_bounds__(256)
bn_s1c_kernel(const float* g, const float* b) { bn_channel<1024, 16>(g_s1c, g, b); }
__global__ void __launch_bounds__(256)
bn_s2_kernel(const float* g, const float* b) { bn_channel<64, 32>(g_s2, g, b); }
__global__ void __launch_bounds__(256)
bn_s3_kernel(const float* g, const float* b) { bn_channel<16, 32>(g_s3, g, b); }

// ---------------- launch ----------------
extern "C" void kernel_launch(void* const* d_in, const int* in_sizes, int n_in,
                              void* d_out, int out_size)
{
    const float* x   = (const float*)d_in[0];
    const float* l1c = (const float*)d_in[1];
    const float* l1l = (const float*)d_in[2];
    const float* c1c = (const float*)d_in[3];
    const float* c1l = (const float*)d_in[4];
    const float* l2c = (const float*)d_in[5];
    const float* l2l = (const float*)d_in[6];
    const float* c2c = (const float*)d_in[7];
    const float* c2l = (const float*)d_in[8];
    const float* l3c = (const float*)d_in[9];
    const float* l3l = (const float*)d_in[10];
    const float* c3c = (const float*)d_in[11];
    const float* c3l = (const float*)d_in[12];
    const float* fc  = (const float*)d_in[13];
    const float* fl  = (const float*)d_in[14];
    const float* g1  = (const float*)d_in[15];
    const float* b1  = (const float*)d_in[16];
    const float* gc1 = (const float*)d_in[17];
    const float* bc1 = (const float*)d_in[18];
    const float* g2  = (const float*)d_in[19];
    const float* b2  = (const float*)d_in[20];
    const float* g3  = (const float*)d_in[21];
    const float* b3  = (const float*)d_in[22];
    float* outp = (float*)d_out;

    // s1 dynamic smem: lote phi 4*48*32 + Mbuf 2*32*256 = 22528 floats = 90112 B
    static bool attr_set = false;
    if (!attr_set) {
        cudaFuncSetAttribute(s1_k, cudaFuncAttributeMaxDynamicSharedMemorySize, 90112);
        attr_set = true;
    }

    // launch order chosen so launch #6 (ncu -s 5 -c 1) is a2_k (stage2 GEMM)
    lsumA_k<<<1024, 256>>>(c1l);                              // 1
    lsumB_k<<<417, 256>>>(l1l, l2l, c2l, l3l, c3l, fl);       // 2
    s1_k<<<1280, 256, 90112>>>(x, l1c, c1c);                  // 3
    bn_s1l_kernel<<<256, 256>>>(g1, b1);                      // 4
    bn_s1c_kernel<<<1024, 256>>>(gc1, bc1);                   // 5
    a2_k<<<2304, 256>>>(l2c, c2c);                            // 6  <- profiled
    b2_k<<<256, 256>>>();                                     // 7
    bn_s2_kernel<<<64, 256>>>(g2, b2);                        // 8
    a3_k<<<576, 256>>>(l3c, c3c);                             // 9
    b3_k<<<64, 256>>>();                                      // 10
    bn_s3_kernel<<<16, 256>>>(g3, b3);                        // 11
    afin_k<<<16, 256>>>(fc);                                  // 12
    bfin_k<<<2, 256>>>(outp);                                 // 13
}